// round 1
// baseline (speedup 1.0000x reference)
#include <cuda_runtime.h>
#include <math.h>
#include <stdint.h>

// Problem constants (fixed by reference setup_inputs)
#define NB 4
#define NS 4096
#define ND 1024
#define NC 512
#define NK 5
#define NROWS (NB * NS)        // 16384

// ---------------------------------------------------------------------------
// Device scratch (allocation-free rule: __device__ globals)
// ---------------------------------------------------------------------------
__device__ float g_mean[NROWS];
__device__ float g_rstd[NROWS];
__device__ float g_conv[(size_t)NROWS * ND];        //  64 MB  (LN+conv output, GEMM1 A)
__device__ float g_gv  [(size_t)NROWS * 2 * ND];    // 128 MB  (GEMM1 output)
__device__ float g_act [(size_t)NROWS * ND];        //  64 MB  (sigmoid(gate)*value, GEMM2 A)
__device__ float g_scale[NB * ND];
__device__ float g_shift[NB * ND];

__device__ __forceinline__ float sigmoidf(float v) {
    return 1.0f / (1.0f + expf(-v));
}

// ---------------------------------------------------------------------------
// FiLM: scale = sigmoid(cond @ scale_w + scale_b), shift = cond @ shift_w + shift_b
// 4096 outputs, dot length 512. One thread per (b,d).
// ---------------------------------------------------------------------------
__global__ void film_kernel(const float* __restrict__ cond,
                            const float* __restrict__ scale_w,
                            const float* __restrict__ scale_b,
                            const float* __restrict__ shift_w,
                            const float* __restrict__ shift_b) {
    int t = blockIdx.x * blockDim.x + threadIdx.x;   // 0..4095
    int b = t >> 10;
    int d = t & (ND - 1);
    const float* cb = cond + b * NC;
    float sa = scale_b[d];
    float sh = shift_b[d];
#pragma unroll 4
    for (int c = 0; c < NC; c++) {
        float cv = cb[c];
        sa = fmaf(cv, scale_w[c * ND + d], sa);
        sh = fmaf(cv, shift_w[c * ND + d], sh);
    }
    g_scale[t] = sigmoidf(sa);
    g_shift[t] = sh;
}

// ---------------------------------------------------------------------------
// LayerNorm stats: per-row mean & rstd over D=1024. 128 threads/row.
// ---------------------------------------------------------------------------
__global__ void stats_kernel(const float* __restrict__ x) {
    int row = blockIdx.x;
    const float* xr = x + (size_t)row * ND;
    int t = threadIdx.x;   // 0..127
    float4 a = *(const float4*)&xr[t * 4];
    float4 c = *(const float4*)&xr[512 + t * 4];
    float s = a.x + a.y + a.z + a.w + c.x + c.y + c.z + c.w;
    float q = a.x * a.x + a.y * a.y + a.z * a.z + a.w * a.w
            + c.x * c.x + c.y * c.y + c.z * c.z + c.w * c.w;
#pragma unroll
    for (int o = 16; o > 0; o >>= 1) {
        s += __shfl_down_sync(0xffffffffu, s, o);
        q += __shfl_down_sync(0xffffffffu, q, o);
    }
    __shared__ float ss[4], sq[4];
    if ((t & 31) == 0) { ss[t >> 5] = s; sq[t >> 5] = q; }
    __syncthreads();
    if (t == 0) {
        float S = ss[0] + ss[1] + ss[2] + ss[3];
        float Q = sq[0] + sq[1] + sq[2] + sq[3];
        float m = S * (1.0f / ND);
        float v = Q * (1.0f / ND) - m * m;
        g_mean[row] = m;
        g_rstd[row] = rsqrtf(v + 1e-5f);
    }
}

// ---------------------------------------------------------------------------
// Fused LayerNorm + depthwise conv (K=5, same padding, zero-pad the
// *normalized* signal). One block per (b,s) row; 256 threads x float4 over D.
// conv[b,s,d] = sum_k norm(x[b, s+k-2, d]) * w[d,k] + dw_b[d]
// ---------------------------------------------------------------------------
__global__ void conv_kernel(const float* __restrict__ x,
                            const float* __restrict__ ln_g,
                            const float* __restrict__ ln_b,
                            const float* __restrict__ dw_w,
                            const float* __restrict__ dw_b) {
    int row = blockIdx.x;            // 0..16383
    int b = row >> 12;               // /4096
    int s = row & (NS - 1);
    int d = threadIdx.x * 4;

    float4 g4 = *(const float4*)&ln_g[d];
    float4 lb4 = *(const float4*)&ln_b[d];
    float4 acc = *(const float4*)&dw_b[d];

    float w0[NK], w1[NK], w2[NK], w3[NK];
#pragma unroll
    for (int k = 0; k < NK; k++) {
        w0[k] = dw_w[(d + 0) * NK + k];
        w1[k] = dw_w[(d + 1) * NK + k];
        w2[k] = dw_w[(d + 2) * NK + k];
        w3[k] = dw_w[(d + 3) * NK + k];
    }

#pragma unroll
    for (int k = 0; k < NK; k++) {
        int r = s + k - 2;
        if ((unsigned)r < (unsigned)NS) {
            int rr = (b << 12) + r;
            float m = g_mean[rr];
            float rs = g_rstd[rr];
            float4 xv = *(const float4*)&x[(size_t)rr * ND + d];
            acc.x = fmaf((xv.x - m) * rs * g4.x + lb4.x, w0[k], acc.x);
            acc.y = fmaf((xv.y - m) * rs * g4.y + lb4.y, w1[k], acc.y);
            acc.z = fmaf((xv.z - m) * rs * g4.z + lb4.z, w2[k], acc.z);
            acc.w = fmaf((xv.w - m) * rs * g4.w + lb4.w, w3[k], acc.w);
        }
    }
    *(float4*)&g_conv[(size_t)row * ND + d] = acc;
}

// ---------------------------------------------------------------------------
// SIMT fp32 GEMM core: C_tile(128x128) = A(MxK) @ B(KxN), 256 threads,
// 8x8 microtile per thread, BK=8, float4 global loads, As stored transposed.
// ---------------------------------------------------------------------------
#define BM 128
#define BN 128
#define BK 8
#define TM 8
#define TN 8

__device__ __forceinline__ void gemm_compute(const float* __restrict__ A,
                                             const float* __restrict__ B,
                                             int N, int K,
                                             float acc[TM][TN]) {
    __shared__ __align__(16) float As[BK][BM];
    __shared__ __align__(16) float Bs[BK][BN];

    int tid = threadIdx.x;           // 0..255
    int tx = tid & 15;               // N direction
    int ty = tid >> 4;               // M direction

    int aRow = tid >> 1;             // 0..127
    int aCol = (tid & 1) * 4;        // 0 or 4
    int bRow = tid >> 5;             // 0..7
    int bCol = (tid & 31) * 4;       // 0..124

    const float* Ab = A + (size_t)(blockIdx.y * BM) * K;
    const float* Bb = B + blockIdx.x * BN;

    for (int k0 = 0; k0 < K; k0 += BK) {
        float4 a4 = *(const float4*)(Ab + (size_t)aRow * K + k0 + aCol);
        As[aCol + 0][aRow] = a4.x;
        As[aCol + 1][aRow] = a4.y;
        As[aCol + 2][aRow] = a4.z;
        As[aCol + 3][aRow] = a4.w;
        *(float4*)&Bs[bRow][bCol] = *(const float4*)(Bb + (size_t)(k0 + bRow) * N + bCol);
        __syncthreads();
#pragma unroll
        for (int kk = 0; kk < BK; kk++) {
            float4 a0 = *(const float4*)&As[kk][ty * TM];
            float4 a1 = *(const float4*)&As[kk][ty * TM + 4];
            float4 b0 = *(const float4*)&Bs[kk][tx * TN];
            float4 b1 = *(const float4*)&Bs[kk][tx * TN + 4];
            float ar[TM] = {a0.x, a0.y, a0.z, a0.w, a1.x, a1.y, a1.z, a1.w};
            float br[TN] = {b0.x, b0.y, b0.z, b0.w, b1.x, b1.y, b1.z, b1.w};
#pragma unroll
            for (int i = 0; i < TM; i++)
#pragma unroll
                for (int j = 0; j < TN; j++)
                    acc[i][j] = fmaf(ar[i], br[j], acc[i][j]);
        }
        __syncthreads();
    }
}

// GEMM1: g_gv = g_conv @ gate_w + gate_b    (M=16384, N=2048, K=1024)
__global__ __launch_bounds__(256, 2)
void sgemm_gate(const float* __restrict__ gate_w,
                const float* __restrict__ gate_b) {
    float acc[TM][TN] = {};
    gemm_compute(g_conv, gate_w, 2 * ND, ND, acc);

    int tid = threadIdx.x;
    int tx = tid & 15, ty = tid >> 4;
    int row0 = blockIdx.y * BM + ty * TM;
    int col0 = blockIdx.x * BN + tx * TN;
    float4 bb0 = *(const float4*)&gate_b[col0];
    float4 bb1 = *(const float4*)&gate_b[col0 + 4];
#pragma unroll
    for (int i = 0; i < TM; i++) {
        float* crow = &g_gv[(size_t)(row0 + i) * (2 * ND) + col0];
        float4 v0 = {acc[i][0] + bb0.x, acc[i][1] + bb0.y, acc[i][2] + bb0.z, acc[i][3] + bb0.w};
        float4 v1 = {acc[i][4] + bb1.x, acc[i][5] + bb1.y, acc[i][6] + bb1.z, acc[i][7] + bb1.w};
        *(float4*)&crow[0] = v0;
        *(float4*)&crow[4] = v1;
    }
}

// act = sigmoid(gv[:, :D]) * gv[:, D:2D]
__global__ void act_kernel() {
    int idx = blockIdx.x * blockDim.x + threadIdx.x;   // over 16384*256 float4s
    int row = idx >> 8;
    int c4 = (idx & 255) * 4;
    const float* gp = &g_gv[(size_t)row * (2 * ND) + c4];
    float4 g = *(const float4*)&gp[0];
    float4 v = *(const float4*)&gp[ND];
    float4 o;
    o.x = sigmoidf(g.x) * v.x;
    o.y = sigmoidf(g.y) * v.y;
    o.z = sigmoidf(g.z) * v.z;
    o.w = sigmoidf(g.w) * v.w;
    *(float4*)&g_act[(size_t)row * ND + c4] = o;
}

// GEMM2: out = x + (g_act @ proj_w + proj_b) * scale[b] + shift[b]
__global__ __launch_bounds__(256, 2)
void sgemm_proj(const float* __restrict__ proj_w,
                const float* __restrict__ proj_b,
                const float* __restrict__ x,
                float* __restrict__ out) {
    float acc[TM][TN] = {};
    gemm_compute(g_act, proj_w, ND, ND, acc);

    int tid = threadIdx.x;
    int tx = tid & 15, ty = tid >> 4;
    int row0 = blockIdx.y * BM + ty * TM;
    int col0 = blockIdx.x * BN + tx * TN;
    int b = row0 >> 12;   // BM=128 divides S=4096, so whole tile is one batch
    float4 pb0 = *(const float4*)&proj_b[col0];
    float4 pb1 = *(const float4*)&proj_b[col0 + 4];
    float4 sc0 = *(const float4*)&g_scale[b * ND + col0];
    float4 sc1 = *(const float4*)&g_scale[b * ND + col0 + 4];
    float4 sh0 = *(const float4*)&g_shift[b * ND + col0];
    float4 sh1 = *(const float4*)&g_shift[b * ND + col0 + 4];
#pragma unroll
    for (int i = 0; i < TM; i++) {
        size_t off = (size_t)(row0 + i) * ND + col0;
        float4 x0 = *(const float4*)&x[off];
        float4 x1 = *(const float4*)&x[off + 4];
        float4 o0, o1;
        o0.x = fmaf(acc[i][0] + pb0.x, sc0.x, x0.x + sh0.x);
        o0.y = fmaf(acc[i][1] + pb0.y, sc0.y, x0.y + sh0.y);
        o0.z = fmaf(acc[i][2] + pb0.z, sc0.z, x0.z + sh0.z);
        o0.w = fmaf(acc[i][3] + pb0.w, sc0.w, x0.w + sh0.w);
        o1.x = fmaf(acc[i][4] + pb1.x, sc1.x, x1.x + sh1.x);
        o1.y = fmaf(acc[i][5] + pb1.y, sc1.y, x1.y + sh1.y);
        o1.z = fmaf(acc[i][6] + pb1.z, sc1.z, x1.z + sh1.z);
        o1.w = fmaf(acc[i][7] + pb1.w, sc1.w, x1.w + sh1.w);
        *(float4*)&out[off]     = o0;
        *(float4*)&out[off + 4] = o1;
    }
}

// ---------------------------------------------------------------------------
// Launch
// ---------------------------------------------------------------------------
extern "C" void kernel_launch(void* const* d_in, const int* in_sizes, int n_in,
                              void* d_out, int out_size) {
    (void)in_sizes; (void)n_in; (void)out_size;
    const float* x       = (const float*)d_in[0];
    const float* cond    = (const float*)d_in[1];
    const float* ln_g    = (const float*)d_in[2];
    const float* ln_b    = (const float*)d_in[3];
    const float* dw_w    = (const float*)d_in[4];
    const float* dw_b    = (const float*)d_in[5];
    const float* gate_w  = (const float*)d_in[6];
    const float* gate_b  = (const float*)d_in[7];
    const float* proj_w  = (const float*)d_in[8];
    const float* proj_b  = (const float*)d_in[9];
    const float* scale_w = (const float*)d_in[10];
    const float* scale_b = (const float*)d_in[11];
    const float* shift_w = (const float*)d_in[12];
    const float* shift_b = (const float*)d_in[13];
    float* out = (float*)d_out;

    film_kernel<<<16, 256>>>(cond, scale_w, scale_b, shift_w, shift_b);
    stats_kernel<<<NROWS, 128>>>(x);
    conv_kernel<<<NROWS, 256>>>(x, ln_g, ln_b, dw_w, dw_b);

    dim3 g1(2 * ND / BN, NROWS / BM);   // (16, 128)
    sgemm_gate<<<g1, 256>>>(gate_w, gate_b);

    act_kernel<<<NROWS * ND / 4 / 256, 256>>>();

    dim3 g2(ND / BN, NROWS / BM);       // (8, 128)
    sgemm_proj<<<g2, 256>>>(proj_w, proj_b, x, out);
}

// round 3
// speedup vs baseline: 4.2460x; 4.2460x over previous
#include <cuda_runtime.h>
#include <cuda_bf16.h>
#include <math.h>
#include <stdint.h>

// Problem constants (fixed by reference setup_inputs)
#define NB 4
#define NS 4096
#define ND 1024
#define NC 512
#define NK 5
#define NROWS (NB * NS)        // 16384

// ---------------------------------------------------------------------------
// Device scratch
// ---------------------------------------------------------------------------
__device__ float g_mean[NROWS];
__device__ float g_rstd[NROWS];
__device__ float g_scale[NB * ND];
__device__ float g_shift[NB * ND];
__device__ float g_gbias[2 * ND];                       // interleaved gate bias
__device__ __nv_bfloat16 g_A1[(size_t)NROWS * ND];      // 32 MB: LN+conv out (GEMM1 A)
__device__ __nv_bfloat16 g_act[(size_t)NROWS * ND];     // 32 MB: silu-gated (GEMM2 A)
__device__ __nv_bfloat16 g_Wg[(size_t)2 * ND * ND];     //  4 MB: gate_w^T interleaved [2048][1024]
__device__ __nv_bfloat16 g_Wp[(size_t)ND * ND];         //  2 MB: proj_w^T [1024][1024]

__device__ __forceinline__ float sigmoidf(float v) { return 1.0f / (1.0f + expf(-v)); }

__device__ __forceinline__ uint32_t smem_to_u32(const void* p) {
    uint32_t a;
    asm("{ .reg .u64 t; cvta.to.shared.u64 t, %1; cvt.u32.u64 %0, t; }"
        : "=r"(a) : "l"(p));
    return a;
}

#define CP_ASYNC16(sm, gm) \
    asm volatile("cp.async.cg.shared.global [%0], [%1], 16;" :: "r"(sm), "l"(gm))
#define CP_COMMIT() asm volatile("cp.async.commit_group;")
#define CP_WAIT(n)  asm volatile("cp.async.wait_group %0;" :: "n"(n))

#define LDMATRIX_X4(r0, r1, r2, r3, addr) \
    asm volatile("ldmatrix.sync.aligned.m8n8.x4.shared.b16 {%0,%1,%2,%3}, [%4];" \
                 : "=r"(r0), "=r"(r1), "=r"(r2), "=r"(r3) : "r"(addr))

#define MMA16816(d, a, b0, b1) \
    asm volatile("mma.sync.aligned.m16n8k16.row.col.f32.bf16.bf16.f32 " \
                 "{%0,%1,%2,%3}, {%4,%5,%6,%7}, {%8,%9}, {%0,%1,%2,%3};" \
                 : "+f"((d)[0]), "+f"((d)[1]), "+f"((d)[2]), "+f"((d)[3]) \
                 : "r"((a)[0]), "r"((a)[1]), "r"((a)[2]), "r"((a)[3]), \
                   "r"(b0), "r"(b1))

// ---------------------------------------------------------------------------
// FiLM
// ---------------------------------------------------------------------------
__global__ void film_kernel(const float* __restrict__ cond,
                            const float* __restrict__ scale_w,
                            const float* __restrict__ scale_b,
                            const float* __restrict__ shift_w,
                            const float* __restrict__ shift_b) {
    int t = blockIdx.x * blockDim.x + threadIdx.x;   // 0..4095
    int b = t >> 10;
    int d = t & (ND - 1);
    const float* cb = cond + b * NC;
    float sa = scale_b[d];
    float sh = shift_b[d];
#pragma unroll 4
    for (int c = 0; c < NC; c++) {
        float cv = cb[c];
        sa = fmaf(cv, scale_w[c * ND + d], sa);
        sh = fmaf(cv, shift_w[c * ND + d], sh);
    }
    g_scale[t] = sigmoidf(sa);
    g_shift[t] = sh;
}

// ---------------------------------------------------------------------------
// LayerNorm stats
// ---------------------------------------------------------------------------
__global__ void stats_kernel(const float* __restrict__ x) {
    int row = blockIdx.x;
    const float* xr = x + (size_t)row * ND;
    int t = threadIdx.x;   // 0..127
    float4 a = *(const float4*)&xr[t * 4];
    float4 c = *(const float4*)&xr[512 + t * 4];
    float s = a.x + a.y + a.z + a.w + c.x + c.y + c.z + c.w;
    float q = a.x * a.x + a.y * a.y + a.z * a.z + a.w * a.w
            + c.x * c.x + c.y * c.y + c.z * c.z + c.w * c.w;
#pragma unroll
    for (int o = 16; o > 0; o >>= 1) {
        s += __shfl_down_sync(0xffffffffu, s, o);
        q += __shfl_down_sync(0xffffffffu, q, o);
    }
    __shared__ float ss[4], sq[4];
    if ((t & 31) == 0) { ss[t >> 5] = s; sq[t >> 5] = q; }
    __syncthreads();
    if (t == 0) {
        float S = ss[0] + ss[1] + ss[2] + ss[3];
        float Q = sq[0] + sq[1] + sq[2] + sq[3];
        float m = S * (1.0f / ND);
        float v = Q * (1.0f / ND) - m * m;
        g_mean[row] = m;
        g_rstd[row] = rsqrtf(v + 1e-5f);
    }
}

// ---------------------------------------------------------------------------
// Fused LayerNorm + depthwise conv (K=5) -> bf16 A1
// ---------------------------------------------------------------------------
__global__ void conv_kernel(const float* __restrict__ x,
                            const float* __restrict__ ln_g,
                            const float* __restrict__ ln_b,
                            const float* __restrict__ dw_w,
                            const float* __restrict__ dw_b) {
    int row = blockIdx.x;            // 0..16383
    int b = row >> 12;
    int s = row & (NS - 1);
    int d = threadIdx.x * 4;

    float4 g4 = *(const float4*)&ln_g[d];
    float4 lb4 = *(const float4*)&ln_b[d];
    float4 acc = *(const float4*)&dw_b[d];

    float w0[NK], w1[NK], w2[NK], w3[NK];
#pragma unroll
    for (int k = 0; k < NK; k++) {
        w0[k] = dw_w[(d + 0) * NK + k];
        w1[k] = dw_w[(d + 1) * NK + k];
        w2[k] = dw_w[(d + 2) * NK + k];
        w3[k] = dw_w[(d + 3) * NK + k];
    }

#pragma unroll
    for (int k = 0; k < NK; k++) {
        int r = s + k - 2;
        if ((unsigned)r < (unsigned)NS) {
            int rr = (b << 12) + r;
            float m = g_mean[rr];
            float rs = g_rstd[rr];
            float4 xv = *(const float4*)&x[(size_t)rr * ND + d];
            acc.x = fmaf((xv.x - m) * rs * g4.x + lb4.x, w0[k], acc.x);
            acc.y = fmaf((xv.y - m) * rs * g4.y + lb4.y, w1[k], acc.y);
            acc.z = fmaf((xv.z - m) * rs * g4.z + lb4.z, w2[k], acc.z);
            acc.w = fmaf((xv.w - m) * rs * g4.w + lb4.w, w3[k], acc.w);
        }
    }
    __align__(8) __nv_bfloat16 h4[4];
    h4[0] = __float2bfloat16(acc.x);
    h4[1] = __float2bfloat16(acc.y);
    h4[2] = __float2bfloat16(acc.z);
    h4[3] = __float2bfloat16(acc.w);
    *(uint2*)&g_A1[(size_t)row * ND + d] = *(uint2*)h4;
}

// ---------------------------------------------------------------------------
// Weight conversion: fp32 [K,N] row-major -> bf16 [N][K] (B operand, K-major).
// Gate variant interleaves: out row 2j <- col j, row 2j+1 <- col j+1024.
// ---------------------------------------------------------------------------
__global__ void convert_gate_kernel(const float* __restrict__ gate_w) {
    __shared__ float t[32][33];
    int n0 = blockIdx.x * 32, k0 = blockIdx.y * 32;
    int tx = threadIdx.x, ty = threadIdx.y;      // 32 x 8
#pragma unroll
    for (int i = 0; i < 32; i += 8)
        t[ty + i][tx] = gate_w[(size_t)(k0 + ty + i) * (2 * ND) + n0 + tx];
    __syncthreads();
#pragma unroll
    for (int i = 0; i < 32; i += 8) {
        int n = n0 + ty + i;
        int rowo = (n < ND) ? 2 * n : 2 * (n - ND) + 1;
        g_Wg[(size_t)rowo * ND + k0 + tx] = __float2bfloat16(t[tx][ty + i]);
    }
}

__global__ void convert_proj_kernel(const float* __restrict__ proj_w) {
    __shared__ float t[32][33];
    int n0 = blockIdx.x * 32, k0 = blockIdx.y * 32;
    int tx = threadIdx.x, ty = threadIdx.y;
#pragma unroll
    for (int i = 0; i < 32; i += 8)
        t[ty + i][tx] = proj_w[(size_t)(k0 + ty + i) * ND + n0 + tx];
    __syncthreads();
#pragma unroll
    for (int i = 0; i < 32; i += 8)
        g_Wp[(size_t)(n0 + ty + i) * ND + k0 + tx] = __float2bfloat16(t[tx][ty + i]);
}

__global__ void bias_kernel(const float* __restrict__ gate_b) {
    int j = blockIdx.x * blockDim.x + threadIdx.x;    // 0..1023
    g_gbias[2 * j]     = gate_b[j];
    g_gbias[2 * j + 1] = gate_b[j + ND];
}

// ---------------------------------------------------------------------------
// mma.sync bf16 tile engine.
// Block 128x128, 8 warps (4 in M x 2 in N), warp tile 32x64.
// BK=32, 4-stage cp.async pipeline. Smem rows: 64B data + 16B pad (80B stride)
// -> conflict-free ldmatrix without swizzle.
// A: [m][k] row-major; B: [n][k] K-major. Both bf16.
// acc[am][atom][4]: am in {0,1} (m16 halves), atom in 0..7 (n8 atoms).
// ---------------------------------------------------------------------------
#define BM 128
#define BN 128
#define BKB 64                    // bytes of K per row per stage (32 bf16)
#define ROWB 80                   // padded row stride
#define STAGES 4
#define STAGE_BYTES (BM * ROWB)   // 10240
#define GEMM_SMEM (2 * STAGES * STAGE_BYTES)   // 81920
#define NCHUNK 32                 // K=1024 / 32

struct Frag { float acc[2][8][4]; };

__device__ __forceinline__ void run_gemm_tile(
    const __nv_bfloat16* __restrict__ A,
    const __nv_bfloat16* __restrict__ B,
    int mBase, int nBase, char* smem, Frag& f)
{
    const int tid = threadIdx.x;
    const int lane = tid & 31;
    const int wid = tid >> 5;
    const int wm = wid & 3;        // 0..3  -> m offset wm*32
    const int wn = wid >> 2;       // 0..1  -> n offset wn*64

    uint32_t smA = smem_to_u32(smem);
    uint32_t smB = smA + STAGES * STAGE_BYTES;

#pragma unroll
    for (int am = 0; am < 2; am++)
#pragma unroll
        for (int at = 0; at < 8; at++)
#pragma unroll
            for (int i = 0; i < 4; i++) f.acc[am][at][i] = 0.0f;

    // global pointers for this thread's cp.async slice
    const char* Ag = (const char*)(A + (size_t)(mBase + (tid >> 1)) * ND);
    const char* Bg = (const char*)(B + (size_t)(nBase + (tid >> 1)) * ND);
    const uint32_t ldRow = (uint32_t)(tid >> 1) * ROWB;
    const uint32_t ldCol = (uint32_t)(tid & 1) * 32;

    // ldmatrix base offsets (within a stage)
    const uint32_t aOff = (uint32_t)(wm * 32 + (lane & 15)) * ROWB + ((lane >> 4) << 4);
    const uint32_t bOff = (uint32_t)(wn * 64 + ((lane >> 4) << 3) + (lane & 7)) * ROWB
                        + (((lane >> 3) & 1) << 4);

    auto issue = [&](int c) {
        uint32_t s = (uint32_t)(c & (STAGES - 1)) * STAGE_BYTES;
        const char* ga = Ag + c * 64 + ldCol;
        const char* gb = Bg + c * 64 + ldCol;
        uint32_t so = s + ldRow + ldCol;
        CP_ASYNC16(smA + so, ga);
        CP_ASYNC16(smA + so + 16, ga + 16);
        CP_ASYNC16(smB + so, gb);
        CP_ASYNC16(smB + so + 16, gb + 16);
        CP_COMMIT();
    };

#pragma unroll
    for (int c = 0; c < STAGES - 1; c++) issue(c);

    for (int c = 0; c < NCHUNK; c++) {
        uint32_t s = (uint32_t)(c & (STAGES - 1)) * STAGE_BYTES;
        CP_WAIT(STAGES - 2);
        __syncthreads();

#pragma unroll
        for (int kk = 0; kk < 2; kk++) {
            uint32_t aF[2][4], bF[4][4];
#pragma unroll
            for (int am = 0; am < 2; am++)
                LDMATRIX_X4(aF[am][0], aF[am][1], aF[am][2], aF[am][3],
                            smA + s + aOff + (uint32_t)am * 16 * ROWB + kk * 32);
#pragma unroll
            for (int bq = 0; bq < 4; bq++)
                LDMATRIX_X4(bF[bq][0], bF[bq][1], bF[bq][2], bF[bq][3],
                            smB + s + bOff + (uint32_t)bq * 16 * ROWB + kk * 32);
#pragma unroll
            for (int am = 0; am < 2; am++)
#pragma unroll
                for (int at = 0; at < 8; at++)
                    MMA16816(f.acc[am][at], aF[am],
                             bF[at >> 1][(at & 1) * 2], bF[at >> 1][(at & 1) * 2 + 1]);
        }

        int nxt = c + STAGES - 1;
        if (nxt < NCHUNK) issue(nxt);
        else CP_COMMIT();   // empty group keeps wait_group counting aligned
    }
    CP_WAIT(0);
}

// ---------------------------------------------------------------------------
// GEMM1: act = silu_gate( A1 @ Wg_interleaved ) -> bf16.
// Lane's accumulator column pair (c0,c1)/(c2,c3) is exactly (gate, value).
// ---------------------------------------------------------------------------
__global__ __launch_bounds__(256)
void gemm_gate_kernel() {
    extern __shared__ __align__(16) char smem[];
    int mBase = blockIdx.y * BM;
    int nBase = blockIdx.x * BN;
    Frag f;
    run_gemm_tile(g_A1, g_Wg, mBase, nBase, smem, f);

    const int lane = threadIdx.x & 31;
    const int wid = threadIdx.x >> 5;
    const int wm = wid & 3, wn = wid >> 2;
    const int rowB = mBase + wm * 32 + (lane >> 2);
    const int colP = (nBase >> 1) + wn * 32 + (lane & 3);     // act column
    const int Jb   = nBase + wn * 64 + (lane & 3) * 2;        // interleaved bias idx

#pragma unroll
    for (int am = 0; am < 2; am++) {
#pragma unroll
        for (int at = 0; at < 8; at++) {
            float gb0 = g_gbias[Jb + at * 8];
            float gb1 = g_gbias[Jb + at * 8 + 1];
            int cc = colP + at * 4;
#pragma unroll
            for (int h = 0; h < 2; h++) {
                int r = rowB + am * 16 + h * 8;
                float gv = f.acc[am][at][2 * h]     + gb0;
                float vv = f.acc[am][at][2 * h + 1] + gb1;
                g_act[(size_t)r * ND + cc] = __float2bfloat16(sigmoidf(gv) * vv);
            }
        }
    }
}

// ---------------------------------------------------------------------------
// GEMM2: out = x + (act @ Wp + proj_b) * scale[b] + shift[b]
// ---------------------------------------------------------------------------
__global__ __launch_bounds__(256)
void gemm_proj_kernel(const float* __restrict__ x,
                      const float* __restrict__ proj_b,
                      float* __restrict__ out) {
    extern __shared__ __align__(16) char smem[];
    int mBase = blockIdx.y * BM;
    int nBase = blockIdx.x * BN;
    Frag f;
    run_gemm_tile(g_act, g_Wp, mBase, nBase, smem, f);

    const int lane = threadIdx.x & 31;
    const int wid = threadIdx.x >> 5;
    const int wm = wid & 3, wn = wid >> 2;
    const int rowB = mBase + wm * 32 + (lane >> 2);
    const int colB = nBase + wn * 64 + (lane & 3) * 2;
    const int b = mBase >> 12;     // BM=128 divides 4096 -> one batch per tile

#pragma unroll
    for (int am = 0; am < 2; am++) {
#pragma unroll
        for (int at = 0; at < 8; at++) {
            int cc = colB + at * 8;
            float pb0 = proj_b[cc],            pb1 = proj_b[cc + 1];
            float sc0 = g_scale[b * ND + cc],  sc1 = g_scale[b * ND + cc + 1];
            float sh0 = g_shift[b * ND + cc],  sh1 = g_shift[b * ND + cc + 1];
#pragma unroll
            for (int h = 0; h < 2; h++) {
                int r = rowB + am * 16 + h * 8;
                size_t off = (size_t)r * ND + cc;
                float2 xv = *(const float2*)&x[off];
                float2 o;
                o.x = fmaf(f.acc[am][at][2 * h]     + pb0, sc0, xv.x + sh0);
                o.y = fmaf(f.acc[am][at][2 * h + 1] + pb1, sc1, xv.y + sh1);
                *(float2*)&out[off] = o;
            }
        }
    }
}

// ---------------------------------------------------------------------------
// Launch
// ---------------------------------------------------------------------------
extern "C" void kernel_launch(void* const* d_in, const int* in_sizes, int n_in,
                              void* d_out, int out_size) {
    (void)in_sizes; (void)n_in; (void)out_size;
    const float* x       = (const float*)d_in[0];
    const float* cond    = (const float*)d_in[1];
    const float* ln_g    = (const float*)d_in[2];
    const float* ln_b    = (const float*)d_in[3];
    const float* dw_w    = (const float*)d_in[4];
    const float* dw_b    = (const float*)d_in[5];
    const float* gate_w  = (const float*)d_in[6];
    const float* gate_b  = (const float*)d_in[7];
    const float* proj_w  = (const float*)d_in[8];
    const float* proj_b  = (const float*)d_in[9];
    const float* scale_w = (const float*)d_in[10];
    const float* scale_b = (const float*)d_in[11];
    const float* shift_w = (const float*)d_in[12];
    const float* shift_b = (const float*)d_in[13];
    float* out = (float*)d_out;

    static int inited = 0;
    if (!inited) {
        cudaFuncSetAttribute(gemm_gate_kernel, cudaFuncAttributeMaxDynamicSharedMemorySize, GEMM_SMEM);
        cudaFuncSetAttribute(gemm_proj_kernel, cudaFuncAttributeMaxDynamicSharedMemorySize, GEMM_SMEM);
        inited = 1;
    }

    film_kernel<<<16, 256>>>(cond, scale_w, scale_b, shift_w, shift_b);
    bias_kernel<<<4, 256>>>(gate_b);
    convert_gate_kernel<<<dim3(2 * ND / 32, ND / 32), dim3(32, 8)>>>(gate_w);
    convert_proj_kernel<<<dim3(ND / 32, ND / 32), dim3(32, 8)>>>(proj_w);
    stats_kernel<<<NROWS, 128>>>(x);
    conv_kernel<<<NROWS, 256>>>(x, ln_g, ln_b, dw_w, dw_b);

    gemm_gate_kernel<<<dim3(2 * ND / BN, NROWS / BM), 256, GEMM_SMEM>>>();
    gemm_proj_kernel<<<dim3(ND / BN, NROWS / BM), 256, GEMM_SMEM>>>(x, proj_b, out);
}